// round 10
// baseline (speedup 1.0000x reference)
#include <cuda_runtime.h>
#include <cstdint>
#include <cstddef>

// ---------------------------------------------------------------------------
// Lfm2ShortConv (sm_103 legacy-tensor path).
//   BCx = hidden @ W_in^T        GEMM1  8192x6144x2048
//   y   = C * conv3(B*x)         fused elementwise
//   out = y @ W_out^T            GEMM2  8192x2048x2048
// R8: tile-major operands + cp.async.bulk feed -> 1548us.
// R9: per-ktile __syncthreads -> full/empty mbarrier pair -> 1457us.
// R10: 16 warps (4/SMSP), warp tile 64x32, acc 64 regs -> per-ktile
// TRYWAIT/LDS latency hidden by 3 sibling warps per scheduler.
// ---------------------------------------------------------------------------

#define SEQ  4096
#define HD   2048
#define MTOT 8192
#define KD   2048
#define NN1  6144
#define NN2  2048

// Scratch (__device__ globals: allocation-free rule), tile-major images
__device__ float g_hidT [(size_t)MTOT * KD];   // A1: 128-row tiles
__device__ float g_winT [(size_t)NN1  * KD];   // B1: 256-row tiles
__device__ float g_woutT[(size_t)NN2  * KD];   // B2: 256-row tiles
__device__ float g_yT   [(size_t)MTOT * KD];   // A2: 128-row tiles
__device__ float g_BCx  [(size_t)MTOT * NN1];  // GEMM1 out, plain row-major

// ---- GEMM tiling ----------------------------------------------------------
constexpr int BM = 128, BN = 256, BK = 32;
constexpr int NTHREADS = 512;                  // 16 warps: 2 (M) x 8 (N)
constexpr int WM_ = 64, WN_ = 32;
constexpr int MT = WM_ / 16;                   // 4
constexpr int NT = WN_ / 8;                    // 4
constexpr int KTILES = KD / BK;                // 64
constexpr int NSTAGE = 4;
constexpr uint32_t A_TILE_B = BM * BK * 4;     // 16384
constexpr uint32_t B_TILE_B = BN * BK * 4;     // 32768
constexpr uint32_t STAGE_B  = A_TILE_B + B_TILE_B;       // 49152
constexpr uint32_t BARS_OFF = NSTAGE * STAGE_B;          // 196608
constexpr uint32_t SMEM_DYN = BARS_OFF + 16 * NSTAGE;    // full[4] + empty[4]

// ---- PTX helpers ----------------------------------------------------------
__device__ __forceinline__ uint32_t smem_u32(const void* p) {
    uint32_t a;
    asm("{ .reg .u64 t; cvta.to.shared.u64 t, %1; cvt.u32.u64 %0, t; }" : "=r"(a) : "l"(p));
    return a;
}
__device__ __forceinline__ uint32_t f2tf(float f) {
    uint32_t u; asm("cvt.rna.tf32.f32 %0, %1;" : "=r"(u) : "f"(f)); return u;
}
__device__ __forceinline__ void bulk_g2s(uint32_t dst, const void* src,
                                         uint32_t bytes, uint32_t bar) {
    asm volatile(
        "cp.async.bulk.shared::cluster.global.mbarrier::complete_tx::bytes "
        "[%0], [%1], %2, [%3];"
        :: "r"(dst), "l"(src), "r"(bytes), "r"(bar) : "memory");
}
#define MBAR_INIT(a, c) \
    asm volatile("mbarrier.init.shared.b64 [%0], %1;" :: "r"(a), "r"(c) : "memory")
#define MBAR_EXPECT_TX(a, b) \
    asm volatile("mbarrier.arrive.expect_tx.shared.b64 _, [%0], %1;" :: "r"(a), "r"(b) : "memory")
#define MBAR_ARRIVE(a) \
    asm volatile("mbarrier.arrive.release.cta.shared.b64 _, [%0];" :: "r"(a) : "memory")
#define FENCE_PROXY_ASYNC() asm volatile("fence.proxy.async.shared::cta;" ::: "memory")
#define MBAR_WAIT(mbar, parity) do {                                          \
    uint32_t _m = (uint32_t)(mbar); uint32_t _p = (uint32_t)(parity);         \
    asm volatile(                                                             \
        "{\n\t.reg .pred P1;\n\t"                                             \
        "WL_%=:\n\t"                                                          \
        "mbarrier.try_wait.parity.acquire.cta.shared::cta.b64 P1, [%0], %1, 0x989680;\n\t" \
        "@P1 bra.uni WD_%=;\n\t"                                              \
        "bra.uni WL_%=;\n\t"                                                  \
        "WD_%=:\n\t}"                                                         \
        :: "r"(_m), "r"(_p) : "memory");                                      \
} while (0)

__device__ __forceinline__ void mma_tf32(float* c, const uint32_t* a, const uint32_t* b) {
    asm volatile(
        "mma.sync.aligned.m16n8k8.row.col.f32.tf32.tf32.f32 "
        "{%0,%1,%2,%3}, {%4,%5,%6,%7}, {%8,%9}, {%0,%1,%2,%3};\n"
        : "+f"(c[0]), "+f"(c[1]), "+f"(c[2]), "+f"(c[3])
        : "r"(a[0]), "r"(a[1]), "r"(a[2]), "r"(a[3]), "r"(b[0]), "r"(b[1]));
}

// ---- TN GEMM: C[M,N] = A[M,K] * B[N,K]^T, tile-major bulk-fed operands ----
__global__ void __launch_bounds__(NTHREADS, 1)
gemm_bulk(const float* __restrict__ At, const float* __restrict__ Bt,
          float* __restrict__ C, int N)
{
    extern __shared__ char smc[];
    float* smf = (float*)smc;
    const uint32_t base = smem_u32(smc);
    const uint32_t fullb = base + BARS_OFF;          // full[s] at +8s
    const uint32_t emptb = fullb + 8 * NSTAGE;       // empty[s] at +8s

    const int tid  = threadIdx.x;
    const int lane = tid & 31;
    const int warp = tid >> 5;
    const int wm = (warp >> 3) * WM_;          // 0 or 64
    const int wn = (warp & 7)  * WN_;          // 0,32,...,224
    const int g  = lane >> 2;                  // 0..7
    const int c  = lane & 3;                   // 0..3

    if (tid == 0) {
        #pragma unroll
        for (int s = 0; s < NSTAGE; s++) {
            MBAR_INIT(fullb + 8 * s, 1u);
            MBAR_INIT(emptb + 8 * s, 16u);     // one arrive per warp
        }
        FENCE_PROXY_ASYNC();
    }
    __syncthreads();

    const float* Abase = At + ((size_t)blockIdx.y * KTILES) * (BM * BK);
    const float* Bbase = Bt + ((size_t)blockIdx.x * KTILES) * (BN * BK);

    auto fill = [&](int kt) {
        const int s = kt & 3;
        const uint32_t sb  = base + (uint32_t)s * STAGE_B;
        const uint32_t bar = fullb + 8 * s;
        MBAR_EXPECT_TX(bar, STAGE_B);
        bulk_g2s(sb,            Abase + (size_t)kt * (BM * BK), A_TILE_B, bar);
        bulk_g2s(sb + A_TILE_B, Bbase + (size_t)kt * (BN * BK), B_TILE_B, bar);
    };

    if (tid == 0) { fill(0); fill(1); fill(2); }

    float acc[MT][NT][4];
    #pragma unroll
    for (int i = 0; i < MT; i++)
        #pragma unroll
        for (int j = 0; j < NT; j++)
            #pragma unroll
            for (int q = 0; q < 4; q++) acc[i][j][q] = 0.f;

    for (int kt = 0; kt < KTILES; ++kt) {
        const int st = kt & 3;
        MBAR_WAIT(fullb + 8 * st, (kt >> 2) & 1);

        const float* as = smf + st * (STAGE_B / 4);
        const float* bs = as + (A_TILE_B / 4);

        // stored layout per tile row: 32 floats = 8 x 16B atoms; atom for
        // (c,h) is (2c+h) ^ (row&7); floats map k = 16h + 4j + c (j=0..3)
        #pragma unroll
        for (int h = 0; h < 2; ++h) {
            const int at = 2 * c + h;
            float4 bf[NT];
            #pragma unroll
            for (int ni = 0; ni < NT; ++ni) {
                const int r = wn + ni * 8 + g;
                bf[ni] = *(const float4*)(bs + r * 32 + ((at ^ g) << 2));
            }
            #pragma unroll
            for (int mi = 0; mi < MT; ++mi) {
                const int r0 = wm + mi * 16 + g;
                float4 a_lo = *(const float4*)(as + r0 * 32 + ((at ^ g) << 2));
                float4 a_hi = *(const float4*)(as + (r0 + 8) * 32 + ((at ^ g) << 2));
                const float* alo = &a_lo.x;
                const float* ahi = &a_hi.x;
                #pragma unroll
                for (int k2 = 0; k2 < 2; ++k2) {
                    uint32_t af[4];
                    af[0] = __float_as_uint(alo[2 * k2 + 0]);
                    af[1] = __float_as_uint(ahi[2 * k2 + 0]);
                    af[2] = __float_as_uint(alo[2 * k2 + 1]);
                    af[3] = __float_as_uint(ahi[2 * k2 + 1]);
                    #pragma unroll
                    for (int ni = 0; ni < NT; ++ni) {
                        const float* bp = &bf[ni].x;
                        uint32_t bfr[2];
                        bfr[0] = __float_as_uint(bp[2 * k2 + 0]);
                        bfr[1] = __float_as_uint(bp[2 * k2 + 1]);
                        mma_tf32(acc[mi][ni], af, bfr);
                    }
                }
            }
        }

        // this warp done with stage st
        if (lane == 0) MBAR_ARRIVE(emptb + 8 * st);

        // producer: refill stage (kt+3) once all 16 warps drained it
        if (tid == 0 && kt + 3 < KTILES) {
            const int fk = kt + 3;
            const int fs = fk & 3;
            if (fk >= NSTAGE)
                MBAR_WAIT(emptb + 8 * fs, ((fk >> 2) + 1) & 1);
            fill(fk);
        }
    }

    // Epilogue: c0=(g,2c) c1=(g,2c+1) c2=(g+8,2c) c3=(g+8,2c+1)
    const int brow = blockIdx.y * BM;
    const int bcol = blockIdx.x * BN;
    #pragma unroll
    for (int mi = 0; mi < MT; ++mi) {
        const int r0 = brow + wm + mi * 16 + g;
        #pragma unroll
        for (int ni = 0; ni < NT; ++ni) {
            const int cc = bcol + wn + ni * 8 + 2 * c;
            *reinterpret_cast<float2*>(C + (size_t)r0 * N + cc) =
                make_float2(acc[mi][ni][0], acc[mi][ni][1]);
            *reinterpret_cast<float2*>(C + (size_t)(r0 + 8) * N + cc) =
                make_float2(acc[mi][ni][2], acc[mi][ni][3]);
        }
    }
}

// ---- prep: fp32 [R,2048] -> tf32-rounded tile-major (TH rows/tile) --------
// element (r,k): tile (r/TH, k/32); within: rr=r%TH, kk=k&31,
// pos p=(kk&3)*8+(kk>>2); atom=(p>>2)^(rr&7); slot = rr*32 + atom*4 + (p&3)
__global__ void __launch_bounds__(256)
prep_tiles(const float4* __restrict__ in, float* __restrict__ out, int n4, int TH)
{
    for (int i = blockIdx.x * blockDim.x + threadIdx.x; i < n4; i += gridDim.x * blockDim.x) {
        float4 v = in[i];
        const int e = i * 4;
        const int r = e >> 11;
        const int k = e & 2047;
        const int rr = r % TH;
        const int q  = (k & 31) >> 2;
        float* tb = out + ((size_t)(r / TH) * KTILES + (k >> 5)) * ((size_t)TH * 32)
                  + rr * 32;
        const int sw = rr & 7;
        const int qa = q >> 2, qb = q & 3;
        tb[(((0 + qa) ^ sw) << 2) + qb] = __uint_as_float(f2tf(v.x));
        tb[(((2 + qa) ^ sw) << 2) + qb] = __uint_as_float(f2tf(v.y));
        tb[(((4 + qa) ^ sw) << 2) + qb] = __uint_as_float(f2tf(v.z));
        tb[(((6 + qa) ^ sw) << 2) + qb] = __uint_as_float(f2tf(v.w));
    }
}

// ---- conv + gating; emits y tf32-rounded into 128-row tile-major ----------
__global__ void __launch_bounds__(256)
conv_gate_kernel(const float* __restrict__ BCx, const float* __restrict__ w,
                 float* __restrict__ yT)
{
    const int idx = blockIdx.x * blockDim.x + threadIdx.x;   // < 8192*2048
    const int h = idx & (HD - 1);
    const int m = idx >> 11;
    const int s = m & (SEQ - 1);

    const float* row = BCx + (size_t)m * NN1;
    const float w0 = w[h * 3 + 0];
    const float w1 = w[h * 3 + 1];
    const float w2 = w[h * 3 + 2];

    float acc = w2 * (row[h] * row[2 * HD + h]);
    if (s >= 1) { const float* r1 = row - NN1;     acc += w1 * (r1[h] * r1[2 * HD + h]); }
    if (s >= 2) { const float* r2 = row - 2 * NN1; acc += w0 * (r2[h] * r2[2 * HD + h]); }
    const float val = acc * row[HD + h];

    const int rr = m & 127;
    const int kk = h & 31;
    const int p  = ((kk & 3) << 3) + (kk >> 2);
    const int atom = ((p >> 2) ^ (rr & 7));
    yT[((size_t)(m >> 7) * KTILES + (h >> 5)) * (128 * 32)
       + rr * 32 + (atom << 2) + (p & 3)] = __uint_as_float(f2tf(val));
}

// ---------------------------------------------------------------------------
extern "C" void kernel_launch(void* const* d_in, const int* in_sizes, int n_in,
                              void* d_out, int out_size)
{
    const float* hs    = (const float*)d_in[0];   // [2,4096,2048]
    const float* Win   = (const float*)d_in[1];   // [6144,2048]
    const float* convw = (const float*)d_in[2];   // [2048,1,3]
    const float* Wout  = (const float*)d_in[3];   // [2048,2048]
    float* out = (float*)d_out;

    float *hidT, *winT, *woutT, *yT, *bcx;
    cudaGetSymbolAddress((void**)&hidT,  g_hidT);
    cudaGetSymbolAddress((void**)&winT,  g_winT);
    cudaGetSymbolAddress((void**)&woutT, g_woutT);
    cudaGetSymbolAddress((void**)&yT,    g_yT);
    cudaGetSymbolAddress((void**)&bcx,   g_BCx);

    cudaFuncSetAttribute(gemm_bulk,
                         cudaFuncAttributeMaxDynamicSharedMemorySize, SMEM_DYN);

    // prep: round to tf32 + tile-major/permuted/swizzled images
    prep_tiles<<<2048, 256>>>((const float4*)hs,   hidT,  MTOT * KD / 4, 128);
    prep_tiles<<<2048, 256>>>((const float4*)Win,  winT,  NN1  * KD / 4, 256);
    prep_tiles<<<2048, 256>>>((const float4*)Wout, woutT, NN2  * KD / 4, 256);

    // GEMM1: BCx = hidden @ W_in^T   [8192 x 6144]
    gemm_bulk<<<dim3(NN1 / BN, MTOT / BM), NTHREADS, SMEM_DYN>>>(hidT, winT, bcx, NN1);

    // conv + gating -> yT (tile-major)
    conv_gate_kernel<<<(MTOT * HD) / 256, 256>>>(bcx, convw, yT);

    // GEMM2: out = y @ W_out^T   [8192 x 2048]
    gemm_bulk<<<dim3(NN2 / BN, MTOT / BM), NTHREADS, SMEM_DYN>>>(yT, woutT, out, NN2);
}

// round 13
// speedup vs baseline: 1.0557x; 1.0557x over previous
#include <cuda_runtime.h>
#include <cstdint>
#include <cstddef>

// ---------------------------------------------------------------------------
// Lfm2ShortConv (sm_103 legacy-tensor path).
//   BCx = hidden @ W_in^T        GEMM1  8192x6144x2048
//   y   = C * conv3(B*x)         fused elementwise
//   out = y @ W_out^T            GEMM2  8192x2048x2048
// R8: tile-major operands + cp.async.bulk feed -> 1548us.
// R9: full/empty mbarrier pipeline -> 1457us.
// R10: 16 warps -> neutral (985us GEMM1 invariant).
// R11/R12: producer role rotates across warps 0-3 (stage fk filled by warp
// fk&3) to kill the warp-0 straggler; float4 conv kernel. (R11 hit an infra
// container failure; this is the same experiment resubmitted.)
// ---------------------------------------------------------------------------

#define SEQ  4096
#define HD   2048
#define MTOT 8192
#define KD   2048
#define NN1  6144
#define NN2  2048

// Scratch (__device__ globals: allocation-free rule), tile-major images
__device__ float g_hidT [(size_t)MTOT * KD];   // A1: 128-row tiles
__device__ float g_winT [(size_t)NN1  * KD];   // B1: 256-row tiles
__device__ float g_woutT[(size_t)NN2  * KD];   // B2: 256-row tiles
__device__ float g_yT   [(size_t)MTOT * KD];   // A2: 128-row tiles
__device__ float g_BCx  [(size_t)MTOT * NN1];  // GEMM1 out, plain row-major

// ---- GEMM tiling ----------------------------------------------------------
constexpr int BM = 128, BN = 256, BK = 32;
constexpr int NTHREADS = 512;                  // 16 warps: 2 (M) x 8 (N)
constexpr int WM_ = 64, WN_ = 32;
constexpr int MT = WM_ / 16;                   // 4
constexpr int NT = WN_ / 8;                    // 4
constexpr int KTILES = KD / BK;                // 64
constexpr int NSTAGE = 4;
constexpr uint32_t A_TILE_B = BM * BK * 4;     // 16384
constexpr uint32_t B_TILE_B = BN * BK * 4;     // 32768
constexpr uint32_t STAGE_B  = A_TILE_B + B_TILE_B;       // 49152
constexpr uint32_t BARS_OFF = NSTAGE * STAGE_B;          // 196608
constexpr uint32_t SMEM_DYN = BARS_OFF + 16 * NSTAGE;    // full[4] + empty[4]

// ---- PTX helpers ----------------------------------------------------------
__device__ __forceinline__ uint32_t smem_u32(const void* p) {
    uint32_t a;
    asm("{ .reg .u64 t; cvta.to.shared.u64 t, %1; cvt.u32.u64 %0, t; }" : "=r"(a) : "l"(p));
    return a;
}
__device__ __forceinline__ uint32_t f2tf(float f) {
    uint32_t u; asm("cvt.rna.tf32.f32 %0, %1;" : "=r"(u) : "f"(f)); return u;
}
__device__ __forceinline__ void bulk_g2s(uint32_t dst, const void* src,
                                         uint32_t bytes, uint32_t bar) {
    asm volatile(
        "cp.async.bulk.shared::cluster.global.mbarrier::complete_tx::bytes "
        "[%0], [%1], %2, [%3];"
        :: "r"(dst), "l"(src), "r"(bytes), "r"(bar) : "memory");
}
#define MBAR_INIT(a, c) \
    asm volatile("mbarrier.init.shared.b64 [%0], %1;" :: "r"(a), "r"(c) : "memory")
#define MBAR_EXPECT_TX(a, b) \
    asm volatile("mbarrier.arrive.expect_tx.shared.b64 _, [%0], %1;" :: "r"(a), "r"(b) : "memory")
#define MBAR_ARRIVE(a) \
    asm volatile("mbarrier.arrive.release.cta.shared.b64 _, [%0];" :: "r"(a) : "memory")
#define FENCE_PROXY_ASYNC() asm volatile("fence.proxy.async.shared::cta;" ::: "memory")
#define MBAR_WAIT(mbar, parity) do {                                          \
    uint32_t _m = (uint32_t)(mbar); uint32_t _p = (uint32_t)(parity);         \
    asm volatile(                                                             \
        "{\n\t.reg .pred P1;\n\t"                                             \
        "WL_%=:\n\t"                                                          \
        "mbarrier.try_wait.parity.acquire.cta.shared::cta.b64 P1, [%0], %1, 0x989680;\n\t" \
        "@P1 bra.uni WD_%=;\n\t"                                              \
        "bra.uni WL_%=;\n\t"                                                  \
        "WD_%=:\n\t}"                                                         \
        :: "r"(_m), "r"(_p) : "memory");                                      \
} while (0)

__device__ __forceinline__ void mma_tf32(float* c, const uint32_t* a, const uint32_t* b) {
    asm volatile(
        "mma.sync.aligned.m16n8k8.row.col.f32.tf32.tf32.f32 "
        "{%0,%1,%2,%3}, {%4,%5,%6,%7}, {%8,%9}, {%0,%1,%2,%3};\n"
        : "+f"(c[0]), "+f"(c[1]), "+f"(c[2]), "+f"(c[3])
        : "r"(a[0]), "r"(a[1]), "r"(a[2]), "r"(a[3]), "r"(b[0]), "r"(b[1]));
}

// ---- TN GEMM: C[M,N] = A[M,K] * B[N,K]^T, tile-major bulk-fed operands ----
__global__ void __launch_bounds__(NTHREADS, 1)
gemm_bulk(const float* __restrict__ At, const float* __restrict__ Bt,
          float* __restrict__ C, int N)
{
    extern __shared__ char smc[];
    float* smf = (float*)smc;
    const uint32_t base = smem_u32(smc);
    const uint32_t fullb = base + BARS_OFF;          // full[s] at +8s
    const uint32_t emptb = fullb + 8 * NSTAGE;       // empty[s] at +8s

    const int tid  = threadIdx.x;
    const int lane = tid & 31;
    const int warp = tid >> 5;
    const int wm = (warp >> 3) * WM_;          // 0 or 64
    const int wn = (warp & 7)  * WN_;          // 0,32,...,224
    const int g  = lane >> 2;                  // 0..7
    const int c  = lane & 3;                   // 0..3

    if (tid == 0) {
        #pragma unroll
        for (int s = 0; s < NSTAGE; s++) {
            MBAR_INIT(fullb + 8 * s, 1u);
            MBAR_INIT(emptb + 8 * s, 16u);     // one arrive per warp
        }
        FENCE_PROXY_ASYNC();
    }
    __syncthreads();

    const float* Abase = At + ((size_t)blockIdx.y * KTILES) * (BM * BK);
    const float* Bbase = Bt + ((size_t)blockIdx.x * KTILES) * (BN * BK);

    auto fill = [&](int kt) {
        const int s = kt & 3;
        const uint32_t sb  = base + (uint32_t)s * STAGE_B;
        const uint32_t bar = fullb + 8 * s;
        MBAR_EXPECT_TX(bar, STAGE_B);
        bulk_g2s(sb,            Abase + (size_t)kt * (BM * BK), A_TILE_B, bar);
        bulk_g2s(sb + A_TILE_B, Bbase + (size_t)kt * (BN * BK), B_TILE_B, bar);
    };

    if (tid == 0) { fill(0); fill(1); fill(2); }

    float acc[MT][NT][4];
    #pragma unroll
    for (int i = 0; i < MT; i++)
        #pragma unroll
        for (int j = 0; j < NT; j++)
            #pragma unroll
            for (int q = 0; q < 4; q++) acc[i][j][q] = 0.f;

    for (int kt = 0; kt < KTILES; ++kt) {
        const int st = kt & 3;
        MBAR_WAIT(fullb + 8 * st, (kt >> 2) & 1);

        const float* as = smf + st * (STAGE_B / 4);
        const float* bs = as + (A_TILE_B / 4);

        // stored layout per tile row: 32 floats = 8 x 16B atoms; atom for
        // (c,h) is (2c+h) ^ (row&7); floats map k = 16h + 4j + c (j=0..3)
        #pragma unroll
        for (int h = 0; h < 2; ++h) {
            const int at = 2 * c + h;
            float4 bf[NT];
            #pragma unroll
            for (int ni = 0; ni < NT; ++ni) {
                const int r = wn + ni * 8 + g;
                bf[ni] = *(const float4*)(bs + r * 32 + ((at ^ g) << 2));
            }
            #pragma unroll
            for (int mi = 0; mi < MT; ++mi) {
                const int r0 = wm + mi * 16 + g;
                float4 a_lo = *(const float4*)(as + r0 * 32 + ((at ^ g) << 2));
                float4 a_hi = *(const float4*)(as + (r0 + 8) * 32 + ((at ^ g) << 2));
                const float* alo = &a_lo.x;
                const float* ahi = &a_hi.x;
                #pragma unroll
                for (int k2 = 0; k2 < 2; ++k2) {
                    uint32_t af[4];
                    af[0] = __float_as_uint(alo[2 * k2 + 0]);
                    af[1] = __float_as_uint(ahi[2 * k2 + 0]);
                    af[2] = __float_as_uint(alo[2 * k2 + 1]);
                    af[3] = __float_as_uint(ahi[2 * k2 + 1]);
                    #pragma unroll
                    for (int ni = 0; ni < NT; ++ni) {
                        const float* bp = &bf[ni].x;
                        uint32_t bfr[2];
                        bfr[0] = __float_as_uint(bp[2 * k2 + 0]);
                        bfr[1] = __float_as_uint(bp[2 * k2 + 1]);
                        mma_tf32(acc[mi][ni], af, bfr);
                    }
                }
            }
        }

        // this warp done with stage st
        if (lane == 0) MBAR_ARRIVE(emptb + 8 * st);

        // rotating producer: stage (kt+3) filled by warp (kt+3)&3, lane 0
        const int fk = kt + 3;
        if (fk < KTILES && warp == (fk & 3) && lane == 0) {
            if (fk >= NSTAGE)
                MBAR_WAIT(emptb + 8 * (fk & 3), ((fk >> 2) + 1) & 1);
            fill(fk);
        }
    }

    // Epilogue: c0=(g,2c) c1=(g,2c+1) c2=(g+8,2c) c3=(g+8,2c+1)
    const int brow = blockIdx.y * BM;
    const int bcol = blockIdx.x * BN;
    #pragma unroll
    for (int mi = 0; mi < MT; ++mi) {
        const int r0 = brow + wm + mi * 16 + g;
        #pragma unroll
        for (int ni = 0; ni < NT; ++ni) {
            const int cc = bcol + wn + ni * 8 + 2 * c;
            *reinterpret_cast<float2*>(C + (size_t)r0 * N + cc) =
                make_float2(acc[mi][ni][0], acc[mi][ni][1]);
            *reinterpret_cast<float2*>(C + (size_t)(r0 + 8) * N + cc) =
                make_float2(acc[mi][ni][2], acc[mi][ni][3]);
        }
    }
}

// ---- prep: fp32 [R,2048] -> tf32-rounded tile-major (TH rows/tile) --------
// element (r,k): tile (r/TH, k/32); within: rr=r%TH, kk=k&31,
// pos p=(kk&3)*8+(kk>>2); atom=(p>>2)^(rr&7); slot = rr*32 + atom*4 + (p&3)
__global__ void __launch_bounds__(256)
prep_tiles(const float4* __restrict__ in, float* __restrict__ out, int n4, int TH)
{
    for (int i = blockIdx.x * blockDim.x + threadIdx.x; i < n4; i += gridDim.x * blockDim.x) {
        float4 v = in[i];
        const int e = i * 4;
        const int r = e >> 11;
        const int k = e & 2047;
        const int rr = r % TH;
        const int q  = (k & 31) >> 2;
        float* tb = out + ((size_t)(r / TH) * KTILES + (k >> 5)) * ((size_t)TH * 32)
                  + rr * 32;
        const int sw = rr & 7;
        const int qa = q >> 2, qb = q & 3;
        tb[(((0 + qa) ^ sw) << 2) + qb] = __uint_as_float(f2tf(v.x));
        tb[(((2 + qa) ^ sw) << 2) + qb] = __uint_as_float(f2tf(v.y));
        tb[(((4 + qa) ^ sw) << 2) + qb] = __uint_as_float(f2tf(v.z));
        tb[(((6 + qa) ^ sw) << 2) + qb] = __uint_as_float(f2tf(v.w));
    }
}

// ---- conv + gating (float4: 4 channels/thread); y -> 128-row tile-major ---
__global__ void __launch_bounds__(256)
conv_gate_kernel(const float* __restrict__ BCx, const float* __restrict__ w,
                 float* __restrict__ yT)
{
    const int t = blockIdx.x * blockDim.x + threadIdx.x;     // < 8192*512
    const int h = (t << 2) & (HD - 1);                       // 4-aligned channel
    const int m = t >> 9;
    const int s = m & (SEQ - 1);

    const float* row = BCx + (size_t)m * NN1 + h;
    const float4 B0 = *(const float4*)(row);
    const float4 C0 = *(const float4*)(row + HD);
    const float4 X0 = *(const float4*)(row + 2 * HD);
    const float4 w0 = *(const float4*)(w + h * 3);           // w[h][0..2], w[h+1][0]
    const float4 w1 = *(const float4*)(w + h * 3 + 4);       // w[h+1][1..2], w[h+2][0..1]
    const float4 w2 = *(const float4*)(w + h * 3 + 8);       // w[h+2][2], w[h+3][0..2]

    float acc0 = w0.z * (B0.x * X0.x);
    float acc1 = w1.y * (B0.y * X0.y);
    float acc2 = w2.x * (B0.z * X0.z);
    float acc3 = w2.w * (B0.w * X0.w);
    if (s >= 1) {
        const float* r1 = row - NN1;
        const float4 B1 = *(const float4*)(r1);
        const float4 X1 = *(const float4*)(r1 + 2 * HD);
        acc0 += w0.y * (B1.x * X1.x);
        acc1 += w1.x * (B1.y * X1.y);
        acc2 += w1.w * (B1.z * X1.z);
        acc3 += w2.z * (B1.w * X1.w);
    }
    if (s >= 2) {
        const float* r2 = row - 2 * NN1;
        const float4 B2 = *(const float4*)(r2);
        const float4 X2 = *(const float4*)(r2 + 2 * HD);
        acc0 += w0.x * (B2.x * X2.x);
        acc1 += w0.w * (B2.y * X2.y);
        acc2 += w1.z * (B2.z * X2.z);
        acc3 += w2.y * (B2.w * X2.w);
    }
    acc0 *= C0.x; acc1 *= C0.y; acc2 *= C0.z; acc3 *= C0.w;

    // tile-major scatter: kk group q = (h&31)>>2; positions q, 8+q, 16+q, 24+q
    const int rr = m & 127;
    const int sw = rr & 7;
    const int q  = (h & 31) >> 2;
    const int qa = q >> 2, qb = q & 3;
    float* tb = yT + ((size_t)(m >> 7) * KTILES + (h >> 5)) * (size_t)(128 * 32)
              + rr * 32;
    tb[(((0 + qa) ^ sw) << 2) + qb] = __uint_as_float(f2tf(acc0));
    tb[(((2 + qa) ^ sw) << 2) + qb] = __uint_as_float(f2tf(acc1));
    tb[(((4 + qa) ^ sw) << 2) + qb] = __uint_as_float(f2tf(acc2));
    tb[(((6 + qa) ^ sw) << 2) + qb] = __uint_as_float(f2tf(acc3));
}

// ---------------------------------------------------------------------------
extern "C" void kernel_launch(void* const* d_in, const int* in_sizes, int n_in,
                              void* d_out, int out_size)
{
    const float* hs    = (const float*)d_in[0];   // [2,4096,2048]
    const float* Win   = (const float*)d_in[1];   // [6144,2048]
    const float* convw = (const float*)d_in[2];   // [2048,1,3]
    const float* Wout  = (const float*)d_in[3];   // [2048,2048]
    float* out = (float*)d_out;

    float *hidT, *winT, *woutT, *yT, *bcx;
    cudaGetSymbolAddress((void**)&hidT,  g_hidT);
    cudaGetSymbolAddress((void**)&winT,  g_winT);
    cudaGetSymbolAddress((void**)&woutT, g_woutT);
    cudaGetSymbolAddress((void**)&yT,    g_yT);
    cudaGetSymbolAddress((void**)&bcx,   g_BCx);

    cudaFuncSetAttribute(gemm_bulk,
                         cudaFuncAttributeMaxDynamicSharedMemorySize, SMEM_DYN);

    // prep: round to tf32 + tile-major/permuted/swizzled images
    prep_tiles<<<2048, 256>>>((const float4*)hs,   hidT,  MTOT * KD / 4, 128);
    prep_tiles<<<2048, 256>>>((const float4*)Win,  winT,  NN1  * KD / 4, 256);
    prep_tiles<<<2048, 256>>>((const float4*)Wout, woutT, NN2  * KD / 4, 256);

    // GEMM1: BCx = hidden @ W_in^T   [8192 x 6144]
    gemm_bulk<<<dim3(NN1 / BN, MTOT / BM), NTHREADS, SMEM_DYN>>>(hidT, winT, bcx, NN1);

    // conv + gating -> yT (tile-major)
    conv_gate_kernel<<<(MTOT * HD / 4) / 256, 256>>>(bcx, convw, yT);

    // GEMM2: out = y @ W_out^T   [8192 x 2048]
    gemm_bulk<<<dim3(NN2 / BN, MTOT / BM), NTHREADS, SMEM_DYN>>>(yT, woutT, out, NN2);
}